// round 2
// baseline (speedup 1.0000x reference)
#include <cuda_runtime.h>
#include <cuda_bf16.h>
#include <cstdint>

// Problem constants (fixed by the reference)
#define N_NODES 50000
#define N_EDGES 800000
#define IN_DIM  128
#define HID     128
#define OUT_DIM 64

// Scratch (device globals — no allocations allowed)
__device__ int   g_idx64;                           // 1 if edge_index is int64
__device__ int   g_deg[N_NODES];
__device__ float g_dinv[N_NODES];
__device__ float g_agg[(size_t)N_NODES * IN_DIM];   // aggregated raw h (25.6 MB)

// ---------------------------------------------------------------------------
// 0) dtype detection: JAX without x64 silently downcasts int64 -> int32.
//    Interpret first 256 entries as int64; valid range => truly int64.
//    (Reads only 2 KB, in-bounds for either dtype.)
// ---------------------------------------------------------------------------
__global__ void k_detect(const void* ei) {
    const long long* e64 = (const long long*)ei;
    int ok64 = 1;
    for (int i = 0; i < 256; i++) {
        long long v = e64[i];
        if (v < 0 || v >= N_NODES) { ok64 = 0; break; }
    }
    g_idx64 = ok64;
}

__device__ __forceinline__ int edge_idx(const void* ei, int i) {
    if (g_idx64) return (int)((const long long*)ei)[i];
    return ((const int*)ei)[i];
}

// ---------------------------------------------------------------------------
// 1) degree init: self-loop contributes 1 to every node
// ---------------------------------------------------------------------------
__global__ void k_deg_init() {
    int i = blockIdx.x * blockDim.x + threadIdx.x;
    if (i < N_NODES) g_deg[i] = 1;
}

// 2) in-degree histogram over destination column (edge_index[1])
__global__ void k_deg_count(const void* __restrict__ ei) {
    int e = blockIdx.x * blockDim.x + threadIdx.x;
    if (e < N_EDGES) {
        int c = edge_idx(ei, N_EDGES + e);
        atomicAdd(&g_deg[c], 1);
    }
}

// 3) dinv = rsqrt(deg)
__global__ void k_dinv() {
    int i = blockIdx.x * blockDim.x + threadIdx.x;
    if (i < N_NODES) g_dinv[i] = rsqrtf((float)g_deg[i]);
}

// ---------------------------------------------------------------------------
// 4) init agg with the self-loop term: agg[i] = h[i] * dinv[i]^2
// ---------------------------------------------------------------------------
__global__ void k_self_init(const float* __restrict__ h) {
    int idx = blockIdx.x * blockDim.x + threadIdx.x;
    if (idx >= N_NODES * 32) return;
    int node = idx >> 5;
    float s = g_dinv[node];
    s = s * s;
    float4 v = ((const float4*)h)[idx];
    v.x *= s; v.y *= s; v.z *= s; v.w *= s;
    ((float4*)g_agg)[idx] = v;
}

// ---------------------------------------------------------------------------
// 5) edge scatter: agg[col] += h[row] * (dinv[row]*dinv[col])
//    one warp per edge; each lane handles one float4 (128 floats / 32 lanes)
//    vectorized L2 reduction: red.global.add.v4.f32 (sm_90+)
// ---------------------------------------------------------------------------
__global__ void __launch_bounds__(256) k_scatter(const float* __restrict__ h,
                                                 const void* __restrict__ ei) {
    int warp = (blockIdx.x * blockDim.x + threadIdx.x) >> 5;
    if (warp >= N_EDGES) return;
    int lane = threadIdx.x & 31;

    int r = edge_idx(ei, warp);
    int c = edge_idx(ei, N_EDGES + warp);
    float norm = g_dinv[r] * g_dinv[c];

    float4 v = __ldg((const float4*)h + (size_t)r * 32 + lane);
    float* dst = g_agg + (size_t)c * IN_DIM + lane * 4;
    asm volatile("red.global.add.v4.f32 [%0], {%1, %2, %3, %4};"
                 :: "l"(dst),
                    "f"(v.x * norm), "f"(v.y * norm),
                    "f"(v.z * norm), "f"(v.w * norm)
                 : "memory");
}

// ---------------------------------------------------------------------------
// 6) fused MLP: out = relu(agg @ W_gcn + b_gcn) @ W_fc + b_fc
//    64 nodes per block, 256 threads; 8x4 register tile phase 1, 8x2 phase 2.
// ---------------------------------------------------------------------------
__global__ void __launch_bounds__(256) k_mlp(const float* __restrict__ Wg,
                                             const float* __restrict__ bg,
                                             const float* __restrict__ Wf,
                                             const float* __restrict__ bf,
                                             float* __restrict__ out) {
    __shared__ float sA[64 * 128];   // 32 KB: input tile, then hidden tile

    int tid = threadIdx.x;
    int tx = tid & 31;       // 0..31
    int ty = tid >> 5;       // 0..7
    int node0 = blockIdx.x * 64;

    // load 64x128 input tile (zero-pad past N)
    for (int i = tid; i < 64 * 32; i += 256) {
        int nn = i >> 5;
        int node = node0 + nn;
        float4 v = make_float4(0.f, 0.f, 0.f, 0.f);
        if (node < N_NODES) v = ((const float4*)g_agg)[(size_t)node * 32 + (i & 31)];
        ((float4*)sA)[i] = v;
    }
    __syncthreads();

    // ---- phase 1: hid = A @ Wg + bg ----
    float acc[8][4];
    {
        float4 b = __ldg((const float4*)bg + tx);
        #pragma unroll
        for (int i = 0; i < 8; i++) {
            acc[i][0] = b.x; acc[i][1] = b.y; acc[i][2] = b.z; acc[i][3] = b.w;
        }
    }
    #pragma unroll 4
    for (int k = 0; k < 128; k++) {
        float4 w = __ldg((const float4*)(Wg + k * 128) + tx);
        #pragma unroll
        for (int i = 0; i < 8; i++) {
            float a = sA[(8 * ty + i) * 128 + k];
            acc[i][0] += a * w.x;
            acc[i][1] += a * w.y;
            acc[i][2] += a * w.z;
            acc[i][3] += a * w.w;
        }
    }
    __syncthreads();

    // relu -> store hidden tile back to smem
    #pragma unroll
    for (int i = 0; i < 8; i++) {
        float4 v;
        v.x = fmaxf(acc[i][0], 0.f);
        v.y = fmaxf(acc[i][1], 0.f);
        v.z = fmaxf(acc[i][2], 0.f);
        v.w = fmaxf(acc[i][3], 0.f);
        ((float4*)sA)[(8 * ty + i) * 32 + tx] = v;
    }
    __syncthreads();

    // ---- phase 2: out = hid @ Wf + bf ----
    float o[8][2];
    {
        float2 b = __ldg((const float2*)bf + tx);
        #pragma unroll
        for (int i = 0; i < 8; i++) { o[i][0] = b.x; o[i][1] = b.y; }
    }
    #pragma unroll 4
    for (int k = 0; k < 128; k++) {
        float2 w = __ldg((const float2*)(Wf + k * 64) + tx);
        #pragma unroll
        for (int i = 0; i < 8; i++) {
            float a = sA[(8 * ty + i) * 128 + k];
            o[i][0] += a * w.x;
            o[i][1] += a * w.y;
        }
    }

    #pragma unroll
    for (int i = 0; i < 8; i++) {
        int node = node0 + 8 * ty + i;
        if (node < N_NODES) {
            float2 v; v.x = o[i][0]; v.y = o[i][1];
            ((float2*)(out))[(size_t)node * 32 + tx] = v;
        }
    }
}

// ---------------------------------------------------------------------------
// launch
// inputs (metadata order): h[f32 N*128], edge_index[2*E, int32 OR int64],
//                          W_gcn[f32 128*128], b_gcn[f32 128],
//                          W_fc[f32 128*64], b_fc[f32 64]
// output: f32 N*64
// ---------------------------------------------------------------------------
extern "C" void kernel_launch(void* const* d_in, const int* in_sizes, int n_in,
                              void* d_out, int out_size) {
    const float* h  = (const float*)d_in[0];
    const void*  ei = d_in[1];
    const float* Wg = (const float*)d_in[2];
    const float* bg = (const float*)d_in[3];
    const float* Wf = (const float*)d_in[4];
    const float* bf = (const float*)d_in[5];
    float* out = (float*)d_out;

    k_detect<<<1, 1>>>(ei);
    k_deg_init<<<(N_NODES + 255) / 256, 256>>>();
    k_deg_count<<<(N_EDGES + 255) / 256, 256>>>(ei);
    k_dinv<<<(N_NODES + 255) / 256, 256>>>();
    k_self_init<<<(N_NODES * 32 + 255) / 256, 256>>>(h);
    // one warp per edge, 8 warps per block
    k_scatter<<<(N_EDGES + 7) / 8, 256>>>(h, ei);
    k_mlp<<<(N_NODES + 63) / 64, 256>>>(Wg, bg, Wf, bf, out);
}